// round 8
// baseline (speedup 1.0000x reference)
#include <cuda_runtime.h>
#include <cstdint>

// BroadcastTC on GB300, round 8: persistent 8-tile blocks with double-buffered
// cp.async input prefetch, overlapping tile i+1's reads with tile i's
// compute + write-out. npairs = B*C = 1,048,576; t1,t2 = 27 fp32 per pair.
//   out1[xy,uv] = sum_k t1[xy*3+k]*t2[k*9+uv] / sqrt(3)   (81 floats)
//   out2[x,u]   = sum_kl t1[x*9+kl]*t2[kl*3+u] / 3        (9 floats)
//   out3        = dot(t1,t2) / sqrt(27)                   (1 float)
// Output layout: [out1 flat | out2 flat | out3 flat].
//
// Role split (warp-uniform): threads p (role 0) and p+64 (role 1) share pair p.

#define PPT 64        // pairs per tile
#define THREADS 128
#define TPB 8         // tiles per block; grid = tiles/TPB = 2048

__device__ __forceinline__ uint32_t smem_u32(const void* p) {
    uint32_t a;
    asm("{ .reg .u64 t; cvta.to.shared.u64 t, %1; cvt.u32.u64 %0, t; }"
        : "=r"(a) : "l"(p));
    return a;
}

__global__ __launch_bounds__(THREADS, 4)
void broadcast_tc_kernel(const float* __restrict__ T1,
                         const float* __restrict__ T2,
                         float* __restrict__ out,
                         int npairs)
{
    // inb[buf]: t1 at floats [0..1727], t2 at [1728..3455] (13824 B each).
    // After a tile's inputs are consumed, the first 256 floats of its buffer
    // are reused as the cross-role partial array ("aux").
    __shared__ __align__(16) float inb[2][PPT * 54];   // 27648 B
    __shared__ __align__(16) float stage[PPT * 81];    // 20736 B  (total 48384 B)

    const int tid  = threadIdx.x;
    const int p    = tid & (PPT - 1);
    const int role = tid >> 6;                  // warp-uniform
    const long long tile0 = (long long)blockIdx.x * TPB;

    const float n1 = 0.5773502691896258f;   // 1/sqrt(3)
    const float n2 = 0.3333333333333333f;   // 1/3
    const float n3 = 0.1924500897298753f;   // 1/sqrt(27)

    // ---- prefetch helper: 864 float4 per tile (432 t1 + 432 t2) ----
    auto prefetch = [&](int buf, long long tile) {
        const float4* g1 = (const float4*)(T1 + tile * PPT * 27);
        const float4* g2 = (const float4*)(T2 + tile * PPT * 27);
        const uint32_t sb = smem_u32(inb[buf]);
        #pragma unroll
        for (int t = 0; t < 7; t++) {
            const int i = tid + t * THREADS;
            if (i < 864) {
                const float4* src = (i < 432) ? (g1 + i) : (g2 + (i - 432));
                asm volatile("cp.async.cg.shared.global [%0], [%1], 16;"
                             :: "r"(sb + i * 16), "l"(src) : "memory");
            }
        }
        asm volatile("cp.async.commit_group;" ::: "memory");
    };

    prefetch(0, tile0);

    for (int it = 0; it < TPB; it++) {
        const int cur = it & 1;
        const long long tile = tile0 + it;
        const long long pp0  = tile * PPT;

        if (it + 1 < TPB) {
            prefetch(cur ^ 1, tile + 1);
            asm volatile("cp.async.wait_group 1;" ::: "memory");
        } else {
            asm volatile("cp.async.wait_group 0;" ::: "memory");
        }
        __syncthreads();   // B1: inb[cur] ready; prior tile's stage reads done

        // ---- gather this thread's operands (stride 27: conflict-free) ----
        float b[27], a[15];   // a[j] = t1[role*12 + j]
        #pragma unroll
        for (int j = 0; j < 27; j++) b[j] = inb[cur][PPT * 27 + p * 27 + j];
        {
            const int ab = p * 27 + role * 12;
            #pragma unroll
            for (int j = 0; j < 15; j++) a[j] = inb[cur][ab + j];
        }
        __syncthreads();   // B2: inb[cur] consumed -> aux region reusable

        float* auxp = inb[cur];   // 256 floats reused for role-0 partials

        if (role == 0) {
            // out1 rows xy = 0..3 -> stage
            #pragma unroll
            for (int xy = 0; xy < 4; xy++) {
                const float c0 = a[xy * 3 + 0] * n1;
                const float c1 = a[xy * 3 + 1] * n1;
                const float c2 = a[xy * 3 + 2] * n1;
                #pragma unroll
                for (int uv = 0; uv < 9; uv++)
                    stage[p * 81 + xy * 9 + uv] =
                        c0 * b[uv] + c1 * b[9 + uv] + c2 * b[18 + uv];
            }
            // out2 x=0 full
            float x0[3];
            #pragma unroll
            for (int u = 0; u < 3; u++) {
                float r = 0.0f;
                #pragma unroll
                for (int kl = 0; kl < 9; kl++) r += a[kl] * b[kl * 3 + u];
                x0[u] = r * n2;
            }
            // out2 x=1 partial, kl=0..2 (t1[9..11])
            #pragma unroll
            for (int u = 0; u < 3; u++)
                auxp[p * 4 + u] = a[9] * b[u] + a[10] * b[3 + u] + a[11] * b[6 + u];
            // out3 partial j=0..11
            float d = 0.0f;
            #pragma unroll
            for (int j = 0; j < 12; j++) d += a[j] * b[j];
            auxp[p * 4 + 3] = d;

            __syncthreads();   // B3: stage + partials published

            // copy out1 (both roles)
            {
                float4* o1 = (float4*)(out + pp0 * 81);
                const float4* sv = (const float4*)stage;
                #pragma unroll
                for (int i = tid; i < PPT * 81 / 4; i += THREADS)
                    __stcs(o1 + i, sv[i]);
            }
            __syncthreads();   // B4: stage free

            // stage out2 x=0 -> slots 0..2
            stage[p * 9 + 0] = x0[0];
            stage[p * 9 + 1] = x0[1];
            stage[p * 9 + 2] = x0[2];
            __syncthreads();   // B5

            {
                float4* o2 = (float4*)(out + (long long)npairs * 81 + pp0 * 9);
                const float4* sv = (const float4*)stage;
                #pragma unroll
                for (int i = tid; i < PPT * 9 / 4; i += THREADS)
                    __stcs(o2 + i, sv[i]);
            }
        } else {
            // a[j] = t1[12+j]
            // out1 rows xy = 4..8: t1[xy*3+k] = a[xy*3-12+k]
            #pragma unroll
            for (int xy = 4; xy < 9; xy++) {
                const float c0 = a[xy * 3 - 12] * n1;
                const float c1 = a[xy * 3 - 11] * n1;
                const float c2 = a[xy * 3 - 10] * n1;
                #pragma unroll
                for (int uv = 0; uv < 9; uv++)
                    stage[p * 81 + xy * 9 + uv] =
                        c0 * b[uv] + c1 * b[9 + uv] + c2 * b[18 + uv];
            }
            // out2 x=1 partial, kl=3..8: t1[9+kl] = t1[12..17] = a[kl-3]
            float x1p[3];
            #pragma unroll
            for (int u = 0; u < 3; u++) {
                float r = 0.0f;
                #pragma unroll
                for (int kl = 3; kl < 9; kl++) r += a[kl - 3] * b[kl * 3 + u];
                x1p[u] = r;
            }
            // out2 x=2 full: t1[18+kl] = a[6+kl]
            float x2[3];
            #pragma unroll
            for (int u = 0; u < 3; u++) {
                float r = 0.0f;
                #pragma unroll
                for (int kl = 0; kl < 9; kl++) r += a[6 + kl] * b[kl * 3 + u];
                x2[u] = r * n2;
            }
            // out3 partial j=12..26
            float d = 0.0f;
            #pragma unroll
            for (int j = 0; j < 15; j++) d += a[j] * b[12 + j];

            __syncthreads();   // B3: stage + role-0 partials visible

            // out3: combine + coalesced streaming store
            __stcs(out + (long long)npairs * 90 + pp0 + p,
                   (d + auxp[p * 4 + 3]) * n3);

            // combine out2 x=1
            float x1[3];
            #pragma unroll
            for (int u = 0; u < 3; u++) x1[u] = (x1p[u] + auxp[p * 4 + u]) * n2;

            // copy out1 (both roles)
            {
                float4* o1 = (float4*)(out + pp0 * 81);
                const float4* sv = (const float4*)stage;
                #pragma unroll
                for (int i = tid; i < PPT * 81 / 4; i += THREADS)
                    __stcs(o1 + i, sv[i]);
            }
            __syncthreads();   // B4: stage free

            // stage out2 x=1, x=2 -> slots 3..8
            stage[p * 9 + 3] = x1[0];
            stage[p * 9 + 4] = x1[1];
            stage[p * 9 + 5] = x1[2];
            stage[p * 9 + 6] = x2[0];
            stage[p * 9 + 7] = x2[1];
            stage[p * 9 + 8] = x2[2];
            __syncthreads();   // B5

            {
                float4* o2 = (float4*)(out + (long long)npairs * 81 + pp0 * 9);
                const float4* sv = (const float4*)stage;
                #pragma unroll
                for (int i = tid; i < PPT * 9 / 4; i += THREADS)
                    __stcs(o2 + i, sv[i]);
            }
        }
    }
}

extern "C" void kernel_launch(void* const* d_in, const int* in_sizes, int n_in,
                              void* d_out, int out_size)
{
    const float* T1 = (const float*)d_in[0];
    const float* T2 = (const float*)d_in[1];
    float* out = (float*)d_out;

    const int npairs = in_sizes[0] / 27;         // 1,048,576
    const int tiles  = npairs / PPT;             // 16384
    const int grid   = tiles / TPB;              // 2048

    broadcast_tc_kernel<<<grid, THREADS>>>(T1, T2, out, npairs);
}

// round 9
// speedup vs baseline: 1.0634x; 1.0634x over previous
#include <cuda_runtime.h>
#include <cstdint>

// BroadcastTC on GB300, round 9: R7 structure + cp.async input staging
// (no LDG->reg->STS round trip) + separate out2 staging buffer (one fewer
// barrier). npairs = B*C = 1,048,576; t1,t2 = 27 fp32 per pair.
//   out1[xy,uv] = sum_k t1[xy*3+k]*t2[k*9+uv] / sqrt(3)   (81 floats)
//   out2[x,u]   = sum_kl t1[x*9+kl]*t2[kl*3+u] / 3        (9 floats)
//   out3        = dot(t1,t2) / sqrt(27)                   (1 float)
// Output layout: [out1 flat | out2 flat | out3 flat].
//
// Role split (warp-uniform): threads p (role 0) and p+64 (role 1) share pair p.
//   role 0: t1[0..11]  -> out1 rows xy=0..3, out2 x=0, x=1 partial(kl=0..2),
//           out3 partial(j=0..11)
//   role 1: t1[12..26] -> out1 rows xy=4..8, out2 x=1 partial(kl=3..8), x=2,
//           out3 partial(j=12..26), combines + stores out3

#define PPB 64
#define THREADS 128

__device__ __forceinline__ uint32_t smem_u32(const void* p) {
    uint32_t a;
    asm("{ .reg .u64 t; cvta.to.shared.u64 t, %1; cvt.u32.u64 %0, t; }"
        : "=r"(a) : "l"(p));
    return a;
}

__global__ __launch_bounds__(THREADS, 8)
void broadcast_tc_kernel(const float* __restrict__ T1,
                         const float* __restrict__ T2,
                         float* __restrict__ out,
                         int npairs)
{
    // s: inputs (t1 at [0..1727], t2 at [1728..3455]) then out1 staging.
    __shared__ __align__(16) float s[PPB * 81];    // 20736 B
    __shared__ __align__(16) float st2[PPB * 9];   // 2304 B (out2 staging)
    __shared__ float aux[PPB * 4];                 // 1024 B (role-0 partials)

    const int tid  = threadIdx.x;
    const int p    = tid & (PPB - 1);
    const int role = tid >> 6;                     // warp-uniform
    const long long p0 = (long long)blockIdx.x * PPB;

    // ---- Phase 1: cp.async input staging (864 float4, L1-bypass) ----
    {
        const float4* g1 = (const float4*)(T1 + p0 * 27);   // 432 float4
        const float4* g2 = (const float4*)(T2 + p0 * 27);   // 432 float4
        const uint32_t sb = smem_u32(s);
        #pragma unroll
        for (int t = 0; t < 7; t++) {
            const int i = tid + t * THREADS;
            if (i < 864) {
                const float4* src = (i < 432) ? (g1 + i) : (g2 + (i - 432));
                asm volatile("cp.async.cg.shared.global [%0], [%1], 16;"
                             :: "r"(sb + i * 16), "l"(src) : "memory");
            }
        }
        asm volatile("cp.async.commit_group;" ::: "memory");
        asm volatile("cp.async.wait_group 0;" ::: "memory");
    }
    __syncthreads();   // B1: inputs visible

    // ---- Phase 2: per-role register gather (stride 27: conflict-free) ----
    float b[27], a[15];   // a[j] = t1[role*12 + j]
    #pragma unroll
    for (int j = 0; j < 27; j++) b[j] = s[PPB * 27 + p * 27 + j];
    {
        const int abase = p * 27 + role * 12;
        #pragma unroll
        for (int j = 0; j < 15; j++) a[j] = s[abase + j];
    }
    __syncthreads();   // B2: inputs consumed; s reusable for out1 staging

    const float n1 = 0.5773502691896258f;   // 1/sqrt(3)
    const float n2 = 0.3333333333333333f;   // 1/3
    const float n3 = 0.1924500897298753f;   // 1/sqrt(27)

    float d;   // out3 partial (both roles)

    if (role == 0) {
        // out1 rows xy = 0..3 -> s
        #pragma unroll
        for (int xy = 0; xy < 4; xy++) {
            const float c0 = a[xy * 3 + 0] * n1;
            const float c1 = a[xy * 3 + 1] * n1;
            const float c2 = a[xy * 3 + 2] * n1;
            #pragma unroll
            for (int uv = 0; uv < 9; uv++)
                s[p * 81 + xy * 9 + uv] = c0 * b[uv] + c1 * b[9 + uv] + c2 * b[18 + uv];
        }
        // out2 x=0 full -> st2 slots 0..2
        #pragma unroll
        for (int u = 0; u < 3; u++) {
            float r = 0.0f;
            #pragma unroll
            for (int kl = 0; kl < 9; kl++) r += a[kl] * b[kl * 3 + u];
            st2[p * 9 + u] = r * n2;
        }
        // out2 x=1 partial, kl=0..2 (t1[9..11]) -> aux
        #pragma unroll
        for (int u = 0; u < 3; u++)
            aux[p * 4 + u] = a[9] * b[u] + a[10] * b[3 + u] + a[11] * b[6 + u];
        // out3 partial j=0..11 -> aux
        d = 0.0f;
        #pragma unroll
        for (int j = 0; j < 12; j++) d += a[j] * b[j];
        aux[p * 4 + 3] = d;
    } else {
        // a[j] = t1[12+j]
        // out1 rows xy = 4..8 -> s
        #pragma unroll
        for (int xy = 4; xy < 9; xy++) {
            const float c0 = a[xy * 3 - 12] * n1;
            const float c1 = a[xy * 3 - 11] * n1;
            const float c2 = a[xy * 3 - 10] * n1;
            #pragma unroll
            for (int uv = 0; uv < 9; uv++)
                s[p * 81 + xy * 9 + uv] = c0 * b[uv] + c1 * b[9 + uv] + c2 * b[18 + uv];
        }
        // out2 x=2 full: t1[18+kl] = a[6+kl] -> st2 slots 6..8
        #pragma unroll
        for (int u = 0; u < 3; u++) {
            float r = 0.0f;
            #pragma unroll
            for (int kl = 0; kl < 9; kl++) r += a[6 + kl] * b[kl * 3 + u];
            st2[p * 9 + 6 + u] = r * n2;
        }
        // out3 partial j=12..26 (kept in reg; combined after B3)
        d = 0.0f;
        #pragma unroll
        for (int j = 0; j < 15; j++) d += a[j] * b[12 + j];
    }
    __syncthreads();   // B3: out1 staged; role-0 partials published

    if (role == 1) {
        // out2 x=1: combine partials -> st2 slots 3..5
        // role-1 part kl=3..8: t1[9+kl] = t1[12..17] = a[kl-3]
        #pragma unroll
        for (int u = 0; u < 3; u++) {
            float r = aux[p * 4 + u];
            #pragma unroll
            for (int kl = 3; kl < 9; kl++) r += a[kl - 3] * b[kl * 3 + u];
            st2[p * 9 + 3 + u] = r * n2;
        }
        // out3: combine + coalesced streaming store
        __stcs(out + (long long)npairs * 90 + p0 + p, (d + aux[p * 4 + 3]) * n3);
    }

    // ---- Copy out1: 1296 float4, fully coalesced ----
    {
        float4* o1 = (float4*)(out + p0 * 81);
        const float4* sv = (const float4*)s;
        #pragma unroll
        for (int i = tid; i < PPB * 81 / 4; i += THREADS)
            __stcs(o1 + i, sv[i]);
    }
    __syncthreads();   // B4: st2 fully written (role-1 slots 3..5)

    // ---- Copy out2: 144 float4 ----
    {
        float4* o2 = (float4*)(out + (long long)npairs * 81 + p0 * 9);
        const float4* sv = (const float4*)st2;
        #pragma unroll
        for (int i = tid; i < PPB * 9 / 4; i += THREADS)
            __stcs(o2 + i, sv[i]);
    }
}

extern "C" void kernel_launch(void* const* d_in, const int* in_sizes, int n_in,
                              void* d_out, int out_size)
{
    const float* T1 = (const float*)d_in[0];
    const float* T2 = (const float*)d_in[1];
    float* out = (float*)d_out;

    const int npairs = in_sizes[0] / 27;     // 1,048,576
    const int grid = npairs / PPB;           // 16384

    broadcast_tc_kernel<<<grid, THREADS>>>(T1, T2, out, npairs);
}